// round 1
// baseline (speedup 1.0000x reference)
#include <cuda_runtime.h>
#include <math.h>

#define BSZ 4
#define NN 256
#define DXD 256
#define DFFD 1024
#define EPSV 1e-5f
#define MROWS (BSZ*NN)   // 1024

// ---------------- scratch (allocation-free) ----------------
__device__ float g_Q   [MROWS*DXD];
__device__ float g_K   [MROWS*DXD];
__device__ float g_V   [MROWS*DXD];
__device__ float g_att [MROWS*DXD];
__device__ float g_proj[MROWS*DXD];
__device__ float g_X1  [MROWS*DXD];
__device__ float g_ffn1[MROWS*DFFD];
__device__ float g_ffn2[MROWS*DXD];

__device__ __forceinline__ float* scratch_ptr(int id) {
    switch (id) {
        case 0: return g_Q;
        case 1: return g_K;
        case 2: return g_V;
        case 3: return g_att;
        case 4: return g_proj;
        case 5: return g_X1;
        case 6: return g_ffn1;
        default: return g_ffn2;
    }
}

// ---------------- generic fp32 GEMM: out = act(A @ W + bias) * rowmask ----------------
// A: [M,K] row-major, W: [K,N] row-major. Block: 256 threads = 256 output cols,
// RPB=8 rows per block. K tiled by 256 through shared memory.
#define RPB 8

__global__ __launch_bounds__(256)
void gemm_bias_kernel(const float* __restrict__ Aext, int Aid,
                      const float* __restrict__ W,
                      const float* __restrict__ bias,
                      float* __restrict__ Oext, int Oid,
                      int K, int N, int act,
                      const float* __restrict__ rowmask)
{
    const float* A = Aext ? Aext : scratch_ptr(Aid);
    float* Out = Oext ? Oext : scratch_ptr(Oid);

    __shared__ float xs[RPB][256];
    const int row0 = blockIdx.x * RPB;
    const int col  = blockIdx.y * 256 + threadIdx.x;

    float acc[RPB];
#pragma unroll
    for (int r = 0; r < RPB; r++) acc[r] = 0.f;

    for (int kt = 0; kt < K; kt += 256) {
#pragma unroll
        for (int r = 0; r < RPB; r++)
            xs[r][threadIdx.x] = A[(size_t)(row0 + r) * K + kt + threadIdx.x];
        __syncthreads();

#pragma unroll 4
        for (int k = 0; k < 256; k++) {
            float w = W[(size_t)(kt + k) * N + col];
#pragma unroll
            for (int r = 0; r < RPB; r++)
                acc[r] = fmaf(xs[r][k], w, acc[r]);
        }
        __syncthreads();
    }

    const float bv = bias[col];
#pragma unroll
    for (int r = 0; r < RPB; r++) {
        float v = acc[r] + bv;
        if (act == 1) v = fmaxf(v, 0.f);
        if (rowmask) v *= rowmask[row0 + r];
        Out[(size_t)(row0 + r) * N + col] = v;
    }
}

// ---------------- attention: per-channel online softmax over j ----------------
// grid = BS*N blocks (one per (b,i)), 256 threads (one per feature channel d).
__global__ __launch_bounds__(256)
void attn_kernel(const float* __restrict__ e_add,
                 const float* __restrict__ e_mul,
                 const float* __restrict__ y_x_add,
                 const float* __restrict__ y_x_mul,
                 const float* __restrict__ node_mask)
{
    const int bi = blockIdx.x;          // b*N + i
    const int b  = bi >> 8;
    const int d  = threadIdx.x;

    __shared__ float sm_mask[NN];
    sm_mask[d] = node_mask[b * NN + d];
    __syncthreads();

    const float mask_i = sm_mask[bi & (NN - 1)];
    const float inv_sqrt_df = 0.1767766952966369f; // 1/sqrt(32)

    const float q = g_Q[(size_t)bi * DXD + d] * inv_sqrt_df;

    const float* pem = e_mul + (size_t)bi * NN * DXD + d;
    const float* pea = e_add + (size_t)bi * NN * DXD + d;
    const float* pk  = g_K   + (size_t)b  * NN * DXD + d;
    const float* pv  = g_V   + (size_t)b  * NN * DXD + d;

    float m = -1e30f, s = 0.f, acc = 0.f;

#pragma unroll 4
    for (int j = 0; j < NN; j++) {
        const float mj = sm_mask[j];
        const float ee = mask_i * mj;
        const float em = pem[(size_t)j * DXD];
        const float ea = pea[(size_t)j * DXD];
        const float kk = pk[(size_t)j * DXD];
        const float vv = pv[(size_t)j * DXD];

        float y = fmaf(q * kk, fmaf(em, ee, 1.f), ea * ee);
        y = (mj > 0.f) ? y : -1e30f;

        const float mn = fmaxf(m, y);
        const float c  = __expf(m - mn);
        const float p  = __expf(y - mn);
        s   = fmaf(s, c, p);
        acc = fmaf(acc, c, p * vv);
        m   = mn;
    }

    const float wv = acc / s;
    const float o  = y_x_add[b * DXD + d] + (y_x_mul[b * DXD + d] + 1.f) * wv;
    g_att[(size_t)bi * DXD + d] = o;
}

// ---------------- layer norm over last dim (256), block per row ----------------
__device__ __forceinline__ float blk_sum256(float v) {
    __shared__ float red[8];
#pragma unroll
    for (int o = 16; o; o >>= 1) v += __shfl_xor_sync(0xffffffffu, v, o);
    if ((threadIdx.x & 31) == 0) red[threadIdx.x >> 5] = v;
    __syncthreads();
    float t = red[0] + red[1] + red[2] + red[3] + red[4] + red[5] + red[6] + red[7];
    __syncthreads();
    return t;
}

__global__ __launch_bounds__(256)
void ln_kernel(const float* __restrict__ Aext, int Aid,
               const float* __restrict__ Bext, int Bid,
               const float* __restrict__ g, const float* __restrict__ beta,
               float* __restrict__ Oext, int Oid)
{
    const float* A = Aext ? Aext : scratch_ptr(Aid);
    const float* B = Bext ? Bext : scratch_ptr(Bid);
    float* Out = Oext ? Oext : scratch_ptr(Oid);

    const int row = blockIdx.x;
    const int t   = threadIdx.x;

    const float x = A[(size_t)row * DXD + t] + B[(size_t)row * DXD + t];
    const float mu = blk_sum256(x) * (1.f / DXD);
    const float dv = x - mu;
    const float var = blk_sum256(dv * dv) * (1.f / DXD);
    Out[(size_t)row * DXD + t] = dv * rsqrtf(var + EPSV) * g[t] + beta[t];
}

// ---------------- launch ----------------
extern "C" void kernel_launch(void* const* d_in, const int* in_sizes, int n_in,
                              void* d_out, int out_size)
{
    const float* X      = (const float*)d_in[0];
    const float* e_add  = (const float*)d_in[1];
    const float* e_mul  = (const float*)d_in[2];
    const float* yxa    = (const float*)d_in[3];
    const float* yxm    = (const float*)d_in[4];
    const float* nmask  = (const float*)d_in[5];
    const float* Wq     = (const float*)d_in[6];
    const float* bq     = (const float*)d_in[7];
    const float* Wk     = (const float*)d_in[8];
    const float* bk     = (const float*)d_in[9];
    const float* Wv     = (const float*)d_in[10];
    const float* bv     = (const float*)d_in[11];
    const float* Wo     = (const float*)d_in[12];
    const float* bo     = (const float*)d_in[13];
    const float* W1     = (const float*)d_in[14];
    const float* b1     = (const float*)d_in[15];
    const float* W2     = (const float*)d_in[16];
    const float* b2     = (const float*)d_in[17];
    const float* g1     = (const float*)d_in[18];
    const float* beta1  = (const float*)d_in[19];
    const float* g2     = (const float*)d_in[20];
    const float* b2ln   = (const float*)d_in[21];
    float* out          = (float*)d_out;

    const dim3 blk(256);
    const dim3 grid_gemm256(MROWS / RPB, 1);   // K or N = 256 GEMMs
    const dim3 grid_ffn1(MROWS / RPB, DFFD / 256);

    // Q, K, V projections (masked)
    gemm_bias_kernel<<<grid_gemm256, blk>>>(X, -1, Wq, bq, nullptr, 0, DXD, DXD, 0, nmask);
    gemm_bias_kernel<<<grid_gemm256, blk>>>(X, -1, Wk, bk, nullptr, 1, DXD, DXD, 0, nmask);
    gemm_bias_kernel<<<grid_gemm256, blk>>>(X, -1, Wv, bv, nullptr, 2, DXD, DXD, 0, nmask);

    // edge-modulated per-channel attention (single pass over e_add/e_mul)
    attn_kernel<<<MROWS, blk>>>(e_add, e_mul, yxa, yxm, nmask);

    // output projection (masked)
    gemm_bias_kernel<<<grid_gemm256, blk>>>(nullptr, 3, Wo, bo, nullptr, 4, DXD, DXD, 0, nmask);

    // LN1: X1 = LN(X + proj)
    ln_kernel<<<MROWS, blk>>>(X, -1, nullptr, 4, g1, beta1, nullptr, 5);

    // FFN
    gemm_bias_kernel<<<grid_ffn1, blk>>>(nullptr, 5, W1, b1, nullptr, 6, DXD, DFFD, 1, nullptr);
    gemm_bias_kernel<<<grid_gemm256, blk>>>(nullptr, 6, W2, b2, nullptr, 7, DFFD, DXD, 0, nullptr);

    // LN2 -> out
    ln_kernel<<<MROWS, blk>>>(nullptr, 5, nullptr, 7, g2, b2ln, out, -1);
}

// round 2
// speedup vs baseline: 1.6560x; 1.6560x over previous
#include <cuda_runtime.h>
#include <math.h>

#define BSZ 4
#define NN 256
#define DXD 256
#define DFFD 1024
#define EPSV 1e-5f
#define MROWS (BSZ*NN)   // 1024

// ---------------- scratch (allocation-free) ----------------
__device__ float g_Q   [MROWS*DXD];
__device__ float g_K   [MROWS*DXD];
__device__ float g_V   [MROWS*DXD];
__device__ float g_att [MROWS*DXD];
__device__ float g_proj[MROWS*DXD];
__device__ float g_X1  [MROWS*DXD];
__device__ float g_ffn1[MROWS*DFFD];
__device__ float g_ffn2[MROWS*DXD];

__device__ __forceinline__ float* scratch_ptr(int id) {
    switch (id) {
        case 0: return g_Q;
        case 1: return g_K;
        case 2: return g_V;
        case 3: return g_att;
        case 4: return g_proj;
        case 5: return g_X1;
        case 6: return g_ffn1;
        default: return g_ffn2;
    }
}

// ---------------- register-tiled SGEMM core ----------------
// Block computes BM x BN tile; each thread TM x TN outputs; K tiled by BK=16.
template<int BM, int BN, int TM, int TN>
__device__ __forceinline__ void gemm_core(const float* __restrict__ A,
                                          const float* __restrict__ W,
                                          const float* __restrict__ bias,
                                          float* __restrict__ Out,
                                          int K, int N, int act,
                                          const float* __restrict__ rowmask,
                                          int row0, int col0)
{
    constexpr int BK  = 16;
    constexpr int NTX = BN / TN;
    constexpr int NTY = BM / TM;
    constexpr int NT  = NTX * NTY;

    __shared__ float As[BK][BM];
    __shared__ float Bs[BK][BN];

    const int tid = threadIdx.x;
    const int tx  = tid % NTX;
    const int ty  = tid / NTX;

    float acc[TM][TN];
#pragma unroll
    for (int m = 0; m < TM; m++)
#pragma unroll
        for (int n = 0; n < TN; n++) acc[m][n] = 0.f;

    for (int kt = 0; kt < K; kt += BK) {
#pragma unroll
        for (int idx = tid; idx < BM * BK; idx += NT) {
            int r = idx / BK, k = idx % BK;
            As[k][r] = A[(size_t)(row0 + r) * K + kt + k];
        }
#pragma unroll
        for (int idx = tid; idx < BK * BN; idx += NT) {
            int k = idx / BN, c = idx % BN;
            Bs[k][c] = W[(size_t)(kt + k) * N + col0 + c];
        }
        __syncthreads();

#pragma unroll
        for (int k = 0; k < BK; k++) {
            float rM[TM], rN[TN];
#pragma unroll
            for (int m = 0; m < TM; m++) rM[m] = As[k][ty * TM + m];
#pragma unroll
            for (int n = 0; n < TN; n++) rN[n] = Bs[k][tx * TN + n];
#pragma unroll
            for (int m = 0; m < TM; m++)
#pragma unroll
                for (int n = 0; n < TN; n++)
                    acc[m][n] = fmaf(rM[m], rN[n], acc[m][n]);
        }
        __syncthreads();
    }

#pragma unroll
    for (int m = 0; m < TM; m++) {
        const int row = row0 + ty * TM + m;
        const float rm = rowmask ? rowmask[row] : 1.f;
#pragma unroll
        for (int n = 0; n < TN; n++) {
            const int col = col0 + tx * TN + n;
            float v = acc[m][n] + bias[col];
            if (act) v = fmaxf(v, 0.f);
            Out[(size_t)row * N + col] = v * rm;
        }
    }
}

template<int BM, int BN, int TM, int TN>
__global__ __launch_bounds__((BM/TM)*(BN/TN))
void sgemm_kernel(const float* __restrict__ Aext, int Aid,
                  const float* __restrict__ W,
                  const float* __restrict__ bias,
                  float* __restrict__ Oext, int Oid,
                  int K, int N, int act,
                  const float* __restrict__ rowmask)
{
    const float* A = Aext ? Aext : scratch_ptr(Aid);
    float* Out = Oext ? Oext : scratch_ptr(Oid);
    gemm_core<BM, BN, TM, TN>(A, W, bias, Out, K, N, act, rowmask,
                              blockIdx.y * BM, blockIdx.x * BN);
}

// fused Q/K/V projections: blockIdx.z selects the weight set + destination
template<int BM, int BN, int TM, int TN>
__global__ __launch_bounds__((BM/TM)*(BN/TN))
void qkv_kernel(const float* __restrict__ X,
                const float* __restrict__ Wq, const float* __restrict__ bq,
                const float* __restrict__ Wk, const float* __restrict__ bk,
                const float* __restrict__ Wv, const float* __restrict__ bv,
                const float* __restrict__ rowmask)
{
    const float* W; const float* b; float* Out;
    if (blockIdx.z == 0)      { W = Wq; b = bq; Out = g_Q; }
    else if (blockIdx.z == 1) { W = Wk; b = bk; Out = g_K; }
    else                      { W = Wv; b = bv; Out = g_V; }
    gemm_core<BM, BN, TM, TN>(X, W, b, Out, DXD, DXD, 0, rowmask,
                              blockIdx.y * BM, blockIdx.x * BN);
}

// ---------------- attention: per-channel softmax over j (no-max, single exp) ----------------
__global__ __launch_bounds__(256)
void attn_kernel(const float* __restrict__ e_add,
                 const float* __restrict__ e_mul,
                 const float* __restrict__ y_x_add,
                 const float* __restrict__ y_x_mul,
                 const float* __restrict__ node_mask)
{
    const int bi = blockIdx.x;          // b*N + i
    const int b  = bi >> 8;
    const int d  = threadIdx.x;

    __shared__ float sm_mask[NN];
    sm_mask[d] = node_mask[b * NN + d];
    __syncthreads();

    const float mask_i = sm_mask[bi & (NN - 1)];
    const float inv_sqrt_df = 0.1767766952966369f; // 1/sqrt(32)

    const float q = g_Q[(size_t)bi * DXD + d] * inv_sqrt_df;

    const float* __restrict__ pem = e_mul + (size_t)bi * NN * DXD + d;
    const float* __restrict__ pea = e_add + (size_t)bi * NN * DXD + d;
    const float* __restrict__ pk  = g_K   + (size_t)b  * NN * DXD + d;
    const float* __restrict__ pv  = g_V   + (size_t)b  * NN * DXD + d;

    float s = 0.f, acc = 0.f;

#pragma unroll 8
    for (int j = 0; j < NN; j++) {
        const float mj = sm_mask[j];
        const float ee = mask_i * mj;
        const float em = pem[(size_t)j * DXD];
        const float ea = pea[(size_t)j * DXD];
        const float kk = pk[(size_t)j * DXD];
        const float vv = pv[(size_t)j * DXD];

        const float y = fmaf(q * kk, fmaf(em, ee, 1.f), ea * ee);
        const float p = (mj > 0.f) ? __expf(y) : 0.f;
        s   += p;
        acc  = fmaf(p, vv, acc);
    }

    const float wv = acc / s;
    const float o  = y_x_add[b * DXD + d] + (y_x_mul[b * DXD + d] + 1.f) * wv;
    g_att[(size_t)bi * DXD + d] = o;
}

// ---------------- layer norm over last dim (256), block per row ----------------
__device__ __forceinline__ float blk_sum256(float v) {
    __shared__ float red[8];
#pragma unroll
    for (int o = 16; o; o >>= 1) v += __shfl_xor_sync(0xffffffffu, v, o);
    if ((threadIdx.x & 31) == 0) red[threadIdx.x >> 5] = v;
    __syncthreads();
    float t = red[0] + red[1] + red[2] + red[3] + red[4] + red[5] + red[6] + red[7];
    __syncthreads();
    return t;
}

__global__ __launch_bounds__(256)
void ln_kernel(const float* __restrict__ Aext, int Aid,
               const float* __restrict__ Bext, int Bid,
               const float* __restrict__ g, const float* __restrict__ beta,
               float* __restrict__ Oext, int Oid)
{
    const float* A = Aext ? Aext : scratch_ptr(Aid);
    const float* B = Bext ? Bext : scratch_ptr(Bid);
    float* Out = Oext ? Oext : scratch_ptr(Oid);

    const int row = blockIdx.x;
    const int t   = threadIdx.x;

    const float x = A[(size_t)row * DXD + t] + B[(size_t)row * DXD + t];
    const float mu = blk_sum256(x) * (1.f / DXD);
    const float dv = x - mu;
    const float var = blk_sum256(dv * dv) * (1.f / DXD);
    Out[(size_t)row * DXD + t] = dv * rsqrtf(var + EPSV) * g[t] + beta[t];
}

// ---------------- launch ----------------
extern "C" void kernel_launch(void* const* d_in, const int* in_sizes, int n_in,
                              void* d_out, int out_size)
{
    const float* X      = (const float*)d_in[0];
    const float* e_add  = (const float*)d_in[1];
    const float* e_mul  = (const float*)d_in[2];
    const float* yxa    = (const float*)d_in[3];
    const float* yxm    = (const float*)d_in[4];
    const float* nmask  = (const float*)d_in[5];
    const float* Wq     = (const float*)d_in[6];
    const float* bq     = (const float*)d_in[7];
    const float* Wk     = (const float*)d_in[8];
    const float* bk     = (const float*)d_in[9];
    const float* Wv     = (const float*)d_in[10];
    const float* bv     = (const float*)d_in[11];
    const float* Wo     = (const float*)d_in[12];
    const float* bo     = (const float*)d_in[13];
    const float* W1     = (const float*)d_in[14];
    const float* b1     = (const float*)d_in[15];
    const float* W2     = (const float*)d_in[16];
    const float* b2     = (const float*)d_in[17];
    const float* g1     = (const float*)d_in[18];
    const float* beta1  = (const float*)d_in[19];
    const float* g2     = (const float*)d_in[20];
    const float* b2ln   = (const float*)d_in[21];
    float* out          = (float*)d_out;

    // fused QKV: grid (N/64, M/64, 3)
    {
        dim3 grid(DXD / 64, MROWS / 64, 3);
        qkv_kernel<64, 64, 4, 4><<<grid, 256>>>(X, Wq, bq, Wk, bk, Wv, bv, nmask);
    }

    // edge-modulated per-channel attention (single pass over e_add/e_mul)
    attn_kernel<<<MROWS, 256>>>(e_add, e_mul, yxa, yxm, nmask);

    // output projection (masked): 32-row tiles -> 128 blocks
    {
        dim3 grid(DXD / 64, MROWS / 32);
        sgemm_kernel<32, 64, 2, 4><<<grid, 256>>>(nullptr, 3, Wo, bo, nullptr, 4,
                                                  DXD, DXD, 0, nmask);
    }

    // LN1: X1 = LN(X + proj)
    ln_kernel<<<MROWS, 256>>>(X, -1, nullptr, 4, g1, beta1, nullptr, 5);

    // FFN1: relu(X1 @ W1 + b1), N=1024 -> 256 blocks
    {
        dim3 grid(DFFD / 64, MROWS / 64);
        sgemm_kernel<64, 64, 4, 4><<<grid, 256>>>(nullptr, 5, W1, b1, nullptr, 6,
                                                  DXD, DFFD, 1, nullptr);
    }

    // FFN2: ffn1 @ W2 + b2, K=1024 -> 32-row tiles, 128 blocks
    {
        dim3 grid(DXD / 64, MROWS / 32);
        sgemm_kernel<32, 64, 2, 4><<<grid, 256>>>(nullptr, 6, W2, b2, nullptr, 7,
                                                  DFFD, DXD, 0, nullptr);
    }

    // LN2 -> out
    ln_kernel<<<MROWS, 256>>>(nullptr, 5, nullptr, 7, g2, b2ln, out, -1);
}

// round 3
// speedup vs baseline: 2.9422x; 1.7767x over previous
#include <cuda_runtime.h>
#include <math.h>

#define BSZ 4
#define NN 256
#define DXD 256
#define DFFD 1024
#define EPSV 1e-5f
#define MROWS (BSZ*NN)   // 1024

// ---------------- scratch (allocation-free) ----------------
__device__ float g_Q   [MROWS*DXD];
__device__ float g_K   [MROWS*DXD];
__device__ float g_V   [MROWS*DXD];
__device__ float g_att [MROWS*DXD];
__device__ float g_proj[MROWS*DXD];
__device__ float g_X1  [MROWS*DXD];
__device__ float g_ffn1[MROWS*DFFD];
__device__ float g_ffn2[MROWS*DXD];

__device__ __forceinline__ float* scratch_ptr(int id) {
    switch (id) {
        case 0: return g_Q;
        case 1: return g_K;
        case 2: return g_V;
        case 3: return g_att;
        case 4: return g_proj;
        case 5: return g_X1;
        case 6: return g_ffn1;
        default: return g_ffn2;
    }
}

// ---------------- tf32 helpers ----------------
__device__ __forceinline__ float f2tf32(float x) {
    unsigned r;
    asm("cvt.rna.tf32.f32 %0, %1;" : "=r"(r) : "f"(x));
    return __uint_as_float(r);
}

__device__ __forceinline__ void mma_tf32(float& c0, float& c1, float& c2, float& c3,
                                         unsigned a0, unsigned a1, unsigned a2, unsigned a3,
                                         unsigned b0, unsigned b1)
{
    asm volatile(
        "mma.sync.aligned.m16n8k8.row.col.f32.tf32.tf32.f32 "
        "{%0,%1,%2,%3}, {%4,%5,%6,%7}, {%8,%9}, {%0,%1,%2,%3};"
        : "+f"(c0), "+f"(c1), "+f"(c2), "+f"(c3)
        : "r"(a0), "r"(a1), "r"(a2), "r"(a3), "r"(b0), "r"(b1));
}

// ---------------- tf32 tensor-core GEMM ----------------
// BM = MT*32, BN = 64, BK = 32, 256 threads = 8 warps in 2(M) x 4(N) layout.
// Warp tile = (MT*16) x 16 -> MT x 2 mma tiles of m16n8k8.
#define SA 36   // As row stride (BK=32 + 4 pad): conflict-free a-frag LDS
#define SB 68   // Bs row stride (BN=64 + 4 pad)

template<int MT>
__device__ __forceinline__ void tgemm_core(const float* __restrict__ A,
                                           const float* __restrict__ W,
                                           const float* __restrict__ bias,
                                           float* __restrict__ Out,
                                           int K, int N, int act,
                                           const float* __restrict__ rowmask,
                                           int row0, int col0)
{
    constexpr int BM = MT * 32;
    __shared__ float As[BM][SA];
    __shared__ float Bs[32][SB];

    const int tid    = threadIdx.x;
    const int lane   = tid & 31;
    const int wid    = tid >> 5;
    const int warp_m = wid & 1;      // 0..1
    const int warp_n = wid >> 1;     // 0..3

    const int lr = lane >> 2;        // 0..7
    const int lc = lane & 3;         // 0..3

    float acc[MT][2][4];
#pragma unroll
    for (int mt = 0; mt < MT; mt++)
#pragma unroll
        for (int nt = 0; nt < 2; nt++)
#pragma unroll
            for (int i = 0; i < 4; i++) acc[mt][nt][i] = 0.f;

    for (int kt = 0; kt < K; kt += 32) {
        // load A tile: BM x 32 floats, float4 per thread
#pragma unroll
        for (int it = 0; it < BM * 32 / 1024; it++) {
            int idx = tid + it * 256;
            int m = idx >> 3, q = idx & 7;
            float4 v = *(const float4*)&A[(size_t)(row0 + m) * K + kt + q * 4];
            As[m][q * 4 + 0] = f2tf32(v.x);
            As[m][q * 4 + 1] = f2tf32(v.y);
            As[m][q * 4 + 2] = f2tf32(v.z);
            As[m][q * 4 + 3] = f2tf32(v.w);
        }
        // load B tile: 32 x 64 floats
#pragma unroll
        for (int it = 0; it < 2; it++) {
            int idx = tid + it * 256;
            int k = idx >> 4, q = idx & 15;
            float4 v = *(const float4*)&W[(size_t)(kt + k) * N + col0 + q * 4];
            Bs[k][q * 4 + 0] = f2tf32(v.x);
            Bs[k][q * 4 + 1] = f2tf32(v.y);
            Bs[k][q * 4 + 2] = f2tf32(v.z);
            Bs[k][q * 4 + 3] = f2tf32(v.w);
        }
        __syncthreads();

#pragma unroll
        for (int ks = 0; ks < 4; ks++) {
            const int k0 = ks * 8;
            unsigned b0[2], b1[2];
#pragma unroll
            for (int nt = 0; nt < 2; nt++) {
                const float* pb = &Bs[k0 + lc][warp_n * 16 + nt * 8 + lr];
                b0[nt] = __float_as_uint(pb[0]);
                b1[nt] = __float_as_uint(pb[4 * SB]);
            }
#pragma unroll
            for (int mt = 0; mt < MT; mt++) {
                const float* pa = &As[warp_m * (BM / 2) + mt * 16 + lr][k0 + lc];
                unsigned a0 = __float_as_uint(pa[0]);
                unsigned a1 = __float_as_uint(pa[8 * SA]);
                unsigned a2 = __float_as_uint(pa[4]);
                unsigned a3 = __float_as_uint(pa[8 * SA + 4]);
#pragma unroll
                for (int nt = 0; nt < 2; nt++)
                    mma_tf32(acc[mt][nt][0], acc[mt][nt][1], acc[mt][nt][2], acc[mt][nt][3],
                             a0, a1, a2, a3, b0[nt], b1[nt]);
            }
        }
        __syncthreads();
    }

    // epilogue
#pragma unroll
    for (int mt = 0; mt < MT; mt++) {
#pragma unroll
        for (int nt = 0; nt < 2; nt++) {
            const int col = col0 + warp_n * 16 + nt * 8 + 2 * lc;
            const float bv0 = bias[col], bv1 = bias[col + 1];
#pragma unroll
            for (int h = 0; h < 2; h++) {
                const int row = row0 + warp_m * (BM / 2) + mt * 16 + lr + h * 8;
                const float rm = rowmask ? rowmask[row] : 1.f;
                float v0 = acc[mt][nt][2 * h + 0] + bv0;
                float v1 = acc[mt][nt][2 * h + 1] + bv1;
                if (act) { v0 = fmaxf(v0, 0.f); v1 = fmaxf(v1, 0.f); }
                Out[(size_t)row * N + col]     = v0 * rm;
                Out[(size_t)row * N + col + 1] = v1 * rm;
            }
        }
    }
}

template<int MT>
__global__ __launch_bounds__(256)
void tgemm_kernel(const float* __restrict__ Aext, int Aid,
                  const float* __restrict__ W,
                  const float* __restrict__ bias,
                  float* __restrict__ Oext, int Oid,
                  int K, int N, int act,
                  const float* __restrict__ rowmask)
{
    const float* A = Aext ? Aext : scratch_ptr(Aid);
    float* Out = Oext ? Oext : scratch_ptr(Oid);
    tgemm_core<MT>(A, W, bias, Out, K, N, act, rowmask,
                   blockIdx.y * MT * 32, blockIdx.x * 64);
}

// fused Q/K/V projections: blockIdx.z selects weight set + destination
__global__ __launch_bounds__(256)
void qkv_kernel(const float* __restrict__ X,
                const float* __restrict__ Wq, const float* __restrict__ bq,
                const float* __restrict__ Wk, const float* __restrict__ bk,
                const float* __restrict__ Wv, const float* __restrict__ bv,
                const float* __restrict__ rowmask)
{
    const float* W; const float* b; float* Out;
    if (blockIdx.z == 0)      { W = Wq; b = bq; Out = g_Q; }
    else if (blockIdx.z == 1) { W = Wk; b = bk; Out = g_K; }
    else                      { W = Wv; b = bv; Out = g_V; }
    tgemm_core<2>(X, W, b, Out, DXD, DXD, 0, rowmask,
                  blockIdx.y * 64, blockIdx.x * 64);
}

// ---------------- attention: float4, 4-way j-parallel, per-channel softmax ----------------
// Block per (b,i): 256 threads = 4 j-groups x 64 channel-quads.
__global__ __launch_bounds__(256)
void attn_kernel(const float* __restrict__ e_add,
                 const float* __restrict__ e_mul,
                 const float* __restrict__ y_x_add,
                 const float* __restrict__ y_x_mul,
                 const float* __restrict__ node_mask)
{
    const int bi  = blockIdx.x;          // b*N + i
    const int b   = bi >> 8;
    const int tid = threadIdx.x;
    const int jg  = tid >> 6;            // 0..3
    const int c0  = (tid & 63) * 4;      // channel quad base

    __shared__ float sm_mask[NN];
    __shared__ float red_s[4][NN];
    __shared__ float red_a[4][NN];

    if (tid < NN) sm_mask[tid] = node_mask[b * NN + tid];
    __syncthreads();

    const float mask_i = sm_mask[bi & (NN - 1)];
    const float inv_sqrt_df = 0.1767766952966369f;

    float4 q = *(const float4*)&g_Q[(size_t)bi * DXD + c0];
    q.x *= inv_sqrt_df; q.y *= inv_sqrt_df; q.z *= inv_sqrt_df; q.w *= inv_sqrt_df;

    const float* __restrict__ pem = e_mul + (size_t)bi * NN * DXD + c0;
    const float* __restrict__ pea = e_add + (size_t)bi * NN * DXD + c0;
    const float* __restrict__ pk  = g_K   + (size_t)b  * NN * DXD + c0;
    const float* __restrict__ pv  = g_V   + (size_t)b  * NN * DXD + c0;

    float4 s   = make_float4(0.f, 0.f, 0.f, 0.f);
    float4 acc = make_float4(0.f, 0.f, 0.f, 0.f);

#pragma unroll 2
    for (int j = jg; j < NN; j += 4) {
        const float mj = sm_mask[j];
        const float ee = mask_i * mj;
        const size_t off = (size_t)j * DXD;
        const float4 em = *(const float4*)(pem + off);
        const float4 ea = *(const float4*)(pea + off);
        const float4 kk = *(const float4*)(pk  + off);
        const float4 vv = *(const float4*)(pv  + off);
        const bool on = (mj > 0.f);

        float y, p;
        y = fmaf(q.x * kk.x, fmaf(em.x, ee, 1.f), ea.x * ee);
        p = on ? __expf(y) : 0.f;  s.x += p;  acc.x = fmaf(p, vv.x, acc.x);
        y = fmaf(q.y * kk.y, fmaf(em.y, ee, 1.f), ea.y * ee);
        p = on ? __expf(y) : 0.f;  s.y += p;  acc.y = fmaf(p, vv.y, acc.y);
        y = fmaf(q.z * kk.z, fmaf(em.z, ee, 1.f), ea.z * ee);
        p = on ? __expf(y) : 0.f;  s.z += p;  acc.z = fmaf(p, vv.z, acc.z);
        y = fmaf(q.w * kk.w, fmaf(em.w, ee, 1.f), ea.w * ee);
        p = on ? __expf(y) : 0.f;  s.w += p;  acc.w = fmaf(p, vv.w, acc.w);
    }

    *(float4*)&red_s[jg][c0] = s;
    *(float4*)&red_a[jg][c0] = acc;
    __syncthreads();

    if (jg == 0) {
        float4 s0 = *(float4*)&red_s[0][c0];
        float4 s1 = *(float4*)&red_s[1][c0];
        float4 s2 = *(float4*)&red_s[2][c0];
        float4 s3 = *(float4*)&red_s[3][c0];
        float4 a0 = *(float4*)&red_a[0][c0];
        float4 a1 = *(float4*)&red_a[1][c0];
        float4 a2 = *(float4*)&red_a[2][c0];
        float4 a3 = *(float4*)&red_a[3][c0];

        const float4 ya = *(const float4*)&y_x_add[b * DXD + c0];
        const float4 ym = *(const float4*)&y_x_mul[b * DXD + c0];

        float4 o;
        o.x = ya.x + (ym.x + 1.f) * ((a0.x + a1.x + a2.x + a3.x) / (s0.x + s1.x + s2.x + s3.x));
        o.y = ya.y + (ym.y + 1.f) * ((a0.y + a1.y + a2.y + a3.y) / (s0.y + s1.y + s2.y + s3.y));
        o.z = ya.z + (ym.z + 1.f) * ((a0.z + a1.z + a2.z + a3.z) / (s0.z + s1.z + s2.z + s3.z));
        o.w = ya.w + (ym.w + 1.f) * ((a0.w + a1.w + a2.w + a3.w) / (s0.w + s1.w + s2.w + s3.w));
        *(float4*)&g_att[(size_t)bi * DXD + c0] = o;
    }
}

// ---------------- single-pass layer norm over last dim (256) ----------------
__global__ __launch_bounds__(256)
void ln_kernel(const float* __restrict__ Aext, int Aid,
               const float* __restrict__ Bext, int Bid,
               const float* __restrict__ g, const float* __restrict__ beta,
               float* __restrict__ Oext, int Oid)
{
    const float* A = Aext ? Aext : scratch_ptr(Aid);
    const float* B = Bext ? Bext : scratch_ptr(Bid);
    float* Out = Oext ? Oext : scratch_ptr(Oid);

    __shared__ float red[16];

    const int row = blockIdx.x;
    const int t   = threadIdx.x;

    const float x = A[(size_t)row * DXD + t] + B[(size_t)row * DXD + t];
    float sx = x, sxx = x * x;
#pragma unroll
    for (int o = 16; o; o >>= 1) {
        sx  += __shfl_xor_sync(0xffffffffu, sx,  o);
        sxx += __shfl_xor_sync(0xffffffffu, sxx, o);
    }
    if ((t & 31) == 0) { red[t >> 5] = sx; red[8 + (t >> 5)] = sxx; }
    __syncthreads();
    sx  = red[0] + red[1] + red[2]  + red[3]  + red[4]  + red[5]  + red[6]  + red[7];
    sxx = red[8] + red[9] + red[10] + red[11] + red[12] + red[13] + red[14] + red[15];

    const float mu  = sx * (1.f / DXD);
    const float var = sxx * (1.f / DXD) - mu * mu;
    Out[(size_t)row * DXD + t] = (x - mu) * rsqrtf(var + EPSV) * g[t] + beta[t];
}

// ---------------- launch ----------------
extern "C" void kernel_launch(void* const* d_in, const int* in_sizes, int n_in,
                              void* d_out, int out_size)
{
    const float* X      = (const float*)d_in[0];
    const float* e_add  = (const float*)d_in[1];
    const float* e_mul  = (const float*)d_in[2];
    const float* yxa    = (const float*)d_in[3];
    const float* yxm    = (const float*)d_in[4];
    const float* nmask  = (const float*)d_in[5];
    const float* Wq     = (const float*)d_in[6];
    const float* bq     = (const float*)d_in[7];
    const float* Wk     = (const float*)d_in[8];
    const float* bk     = (const float*)d_in[9];
    const float* Wv     = (const float*)d_in[10];
    const float* bv     = (const float*)d_in[11];
    const float* Wo     = (const float*)d_in[12];
    const float* bo     = (const float*)d_in[13];
    const float* W1     = (const float*)d_in[14];
    const float* b1     = (const float*)d_in[15];
    const float* W2     = (const float*)d_in[16];
    const float* b2     = (const float*)d_in[17];
    const float* g1     = (const float*)d_in[18];
    const float* beta1  = (const float*)d_in[19];
    const float* g2     = (const float*)d_in[20];
    const float* b2ln   = (const float*)d_in[21];
    float* out          = (float*)d_out;

    // fused QKV (tf32): grid (N/64, M/64, 3) = 192 blocks
    qkv_kernel<<<dim3(DXD / 64, MROWS / 64, 3), 256>>>(X, Wq, bq, Wk, bk, Wv, bv, nmask);

    // edge-modulated per-channel attention
    attn_kernel<<<MROWS, 256>>>(e_add, e_mul, yxa, yxm, nmask);

    // output projection (masked): BM=32 -> 128 blocks
    tgemm_kernel<1><<<dim3(DXD / 64, MROWS / 32), 256>>>(nullptr, 3, Wo, bo, nullptr, 4,
                                                         DXD, DXD, 0, nmask);

    // LN1: X1 = LN(X + proj)
    ln_kernel<<<MROWS, 256>>>(X, -1, nullptr, 4, g1, beta1, nullptr, 5);

    // FFN1: relu(X1 @ W1 + b1): 16x16 = 256 blocks
    tgemm_kernel<2><<<dim3(DFFD / 64, MROWS / 64), 256>>>(nullptr, 5, W1, b1, nullptr, 6,
                                                          DXD, DFFD, 1, nullptr);

    // FFN2: BM=32 -> 128 blocks, K=1024
    tgemm_kernel<1><<<dim3(DXD / 64, MROWS / 32), 256>>>(nullptr, 6, W2, b2, nullptr, 7,
                                                         DFFD, DXD, 0, nullptr);

    // LN2 -> out
    ln_kernel<<<MROWS, 256>>>(nullptr, 5, nullptr, 7, g2, b2ln, out, -1);
}